// round 15
// baseline (speedup 1.0000x reference)
#include <cuda_runtime.h>
#include <cuda_fp16.h>
#include <math_constants.h>

#define NE 100000
#define NR 1000
#define EC 1000000
#define HID 128
#define OUTD 256
#define N2 (2 * NE)
#define SCAN_B 1024
#define SCAN_NB ((N2 + SCAN_B - 1) / SCAN_B)   // 196
#define RT 8                                    // relations per MLP block

// block-range dispatch for the fused front kernel
#define MLP_NB 125
#define NS_NB  ((NE + 31) / 32)                // 3125
#define RS_NB  ((NR + 31) / 32)                // 32
#define H_NB   ((EC + 1023) / 1024)            // 977
#define FRONT_NB (MLP_NB + NS_NB + RS_NB + H_NB)

#define NSTRIP (NE / 16)                        // 6250 GEMM row-strips

// ---- scratch (device globals: allocation-free) ----
__device__ float  g_eh[NE];
__device__ float  g_et[NE];
__device__ float  g_er[NR];
__device__ __half g_msg16[NR * HID];   // fp16 msg table (256 KB)
__device__ __half g_agg[(size_t)NE * OUTD]; // fp16 [aggH|aggT] (51 MB)
__device__ uint2  g_wf[16 * 32 * 32];  // W_r in mma fragment order (128 KB)
__device__ int    g_hist[N2];
__device__ int    g_off[N2];
__device__ int    g_cur[N2];
__device__ float2 g_pk[2 * EC];        // per-slot packed (logit, rel-bits)
__device__ int    g_part[SCAN_NB];
__device__ int    g_partoff[SCAN_NB];

// ---- zero histograms ----
__global__ void k_zero() {
    int i = blockIdx.x * 1024 + threadIdx.x;
    if (i < N2) g_hist[i] = 0;
}

// ---- pre-swizzle W_r into m16n8k16 B-fragment order ----
// idx = (kt*32 + ntile)*32 + lane ; B frag: b0b1 = W[k0..k0+1][n], b2b3 = W[k0+8..9][n]
__global__ void k_wf(const float* __restrict__ Wr) {
    int idx = blockIdx.x * 512 + threadIdx.x;
    if (idx >= 16 * 32 * 32) return;
    int lane = idx & 31;
    int ntg  = (idx >> 5) & 31;
    int kt   = idx >> 10;
    int k0 = kt * 16 + (lane & 3) * 2;
    int n  = ntg * 8 + (lane >> 2);
    __half2 r0 = __floats2half2_rn(Wr[k0 * 256 + n],       Wr[(k0 + 1) * 256 + n]);
    __half2 r1 = __floats2half2_rn(Wr[(k0 + 8) * 256 + n], Wr[(k0 + 9) * 256 + n]);
    g_wf[idx] = make_uint2(*(unsigned*)&r0, *(unsigned*)&r1);
}

// ---- fused front: relation MLP (msg only) + node/rel scores + hist count ----
__global__ __launch_bounds__(1024) void k_front(
        const float* __restrict__ xr,
        const float* __restrict__ W1, const float* __restrict__ b1,
        const float* __restrict__ W2, const float* __restrict__ b2,
        const float* __restrict__ xe,
        const float* __restrict__ wah, const float* __restrict__ wat,
        const float* __restrict__ war,
        const int* __restrict__ ei) {
    __shared__ float xs[RT][HID];
    __shared__ float hs[RT][2 * HID];
    __shared__ float red[8192];
    int bid = blockIdx.x;
    int tid = threadIdx.x;

    if (bid < MLP_NB) {
        int r0 = bid * RT;
        int rh = tid >> 8;               // relation subset: rels rh*2, rh*2+1

        for (int i = tid; i < RT * HID; i += 1024) {
            int rr = i >> 7, c = i & 127;
            xs[rr][c] = xr[(size_t)(r0 + rr) * HID + c];
        }
        __syncthreads();

        // layer 1
        {
            int kk = (tid >> 6) & 3;
            int u  = tid & 63;
            float4 acc[2];
            #pragma unroll
            for (int i = 0; i < 2; i++) acc[i] = make_float4(0.f, 0.f, 0.f, 0.f);
            #pragma unroll 4
            for (int m = 0; m < 32; m++) {
                int k = kk + 4 * m;
                float4 w = *(const float4*)&W1[k * 256 + 4 * u];
                #pragma unroll
                for (int i = 0; i < 2; i++) {
                    float x = xs[rh * 2 + i][k];
                    acc[i].x += x * w.x; acc[i].y += x * w.y;
                    acc[i].z += x * w.z; acc[i].w += x * w.w;
                }
            }
            #pragma unroll
            for (int i = 0; i < 2; i++)
                *(float4*)&red[(kk * 8 + rh * 2 + i) * 256 + 4 * u] = acc[i];
            __syncthreads();
            #pragma unroll
            for (int p = 0; p < 2; p++) {
                int idx = p * 1024 + tid;
                int i = idx >> 8, c = idx & 255;
                hs[i][c] = b1[c] + red[(0 + i) * 256 + c] + red[(8 + i) * 256 + c]
                         + red[(16 + i) * 256 + c] + red[(24 + i) * 256 + c];
            }
            __syncthreads();
        }

        // layer 2 + residual -> msg, stored fp16
        {
            int jj = (tid >> 5) & 7;
            int u  = tid & 31;
            float4 acc[2];
            #pragma unroll
            for (int i = 0; i < 2; i++) acc[i] = make_float4(0.f, 0.f, 0.f, 0.f);
            #pragma unroll 4
            for (int m = 0; m < 32; m++) {
                int j = jj + 8 * m;
                float4 w = *(const float4*)&W2[j * 128 + 4 * u];
                #pragma unroll
                for (int i = 0; i < 2; i++) {
                    float x = hs[rh * 2 + i][j];
                    acc[i].x += x * w.x; acc[i].y += x * w.y;
                    acc[i].z += x * w.z; acc[i].w += x * w.w;
                }
            }
            #pragma unroll
            for (int i = 0; i < 2; i++)
                *(float4*)&red[(jj * 8 + rh * 2 + i) * 128 + 4 * u] = acc[i];
            __syncthreads();
            {
                int i = tid >> 7, c = tid & 127;   // 1024 outputs
                float v = b2[c];
                #pragma unroll
                for (int g = 0; g < 8; g++) v += red[(g * 8 + i) * 128 + c];
                g_msg16[(size_t)(r0 + i) * HID + c] = __float2half(xs[i][c] + v);
            }
        }
    } else if (bid < MLP_NB + NS_NB) {
        int warp = (bid - MLP_NB) * 32 + (tid >> 5);
        int lane = tid & 31;
        if (warp < NE) {
            const float4* row = (const float4*)(xe + (size_t)warp * HID);
            float4 v = row[lane];
            float4 a = ((const float4*)wah)[lane];
            float4 b = ((const float4*)wat)[lane];
            float sh = v.x * a.x + v.y * a.y + v.z * a.z + v.w * a.w;
            float st = v.x * b.x + v.y * b.y + v.z * b.z + v.w * b.w;
            #pragma unroll
            for (int o = 16; o; o >>= 1) {
                sh += __shfl_xor_sync(0xFFFFFFFFu, sh, o);
                st += __shfl_xor_sync(0xFFFFFFFFu, st, o);
            }
            if (lane == 0) { g_eh[warp] = sh; g_et[warp] = st; }
        }
    } else if (bid < MLP_NB + NS_NB + RS_NB) {
        int warp = (bid - MLP_NB - NS_NB) * 32 + (tid >> 5);
        int lane = tid & 31;
        if (warp < NR) {
            const float4* row = (const float4*)(xr + (size_t)warp * HID);
            float4 v = row[lane];
            float4 a = ((const float4*)war)[lane];
            float s = v.x * a.x + v.y * a.y + v.z * a.z + v.w * a.w;
            #pragma unroll
            for (int o = 16; o; o >>= 1) s += __shfl_xor_sync(0xFFFFFFFFu, s, o);
            if (lane == 0) g_er[warp] = s;
        }
    } else {
        int e = (bid - MLP_NB - NS_NB - RS_NB) * 1024 + tid;
        if (e < EC) {
            atomicAdd(&g_hist[ei[e]], 1);
            atomicAdd(&g_hist[NE + ei[EC + e]], 1);
        }
    }
}

// ---- scan stage 1 ----
__global__ void k_scan1() {
    __shared__ int sh[SCAN_B];
    int t = threadIdx.x;
    int i = blockIdx.x * SCAN_B + t;
    int v = (i < N2) ? g_hist[i] : 0;
    sh[t] = v;
    __syncthreads();
    #pragma unroll
    for (int d = 1; d < SCAN_B; d <<= 1) {
        int x = (t >= d) ? sh[t - d] : 0;
        __syncthreads();
        sh[t] += x;
        __syncthreads();
    }
    if (i < N2) g_off[i] = sh[t] - v;
    if (t == SCAN_B - 1) g_part[blockIdx.x] = sh[t];
}

// ---- scan stage 2 ----
__global__ void k_scan2() {
    __shared__ int sh[256];
    int t = threadIdx.x;
    int v = (t < SCAN_NB) ? g_part[t] : 0;
    sh[t] = v;
    __syncthreads();
    #pragma unroll
    for (int d = 1; d < 256; d <<= 1) {
        int x = (t >= d) ? sh[t - d] : 0;
        __syncthreads();
        sh[t] += x;
        __syncthreads();
    }
    if (t < SCAN_NB) g_partoff[t] = sh[t] - v;
}

// ---- scan stage 3 ----
__global__ void k_scan3() {
    int i = blockIdx.x * blockDim.x + threadIdx.x;
    if (i < N2) {
        int o = g_off[i] + g_partoff[i / SCAN_B];
        g_off[i] = o;
        g_cur[i] = o;
    }
}

// ---- fused CSR fill + logits ----
__global__ void k_fill(const int* __restrict__ ei, const int* __restrict__ rel) {
    int e = blockIdx.x * blockDim.x + threadIdx.x;
    if (e >= EC) return;
    int h = ei[e], t = ei[EC + e], r = rel[e];
    float er = g_er[r];
    float rbits = __int_as_float(r);
    float lh = g_eh[h] + er;
    lh = lh > 0.0f ? lh : 0.01f * lh;
    float lt = g_et[t] + er;
    lt = lt > 0.0f ? lt : 0.01f * lt;
    int p = atomicAdd(&g_cur[h], 1);
    g_pk[p] = make_float2(lh, rbits);
    int q = atomicAdd(&g_cur[NE + t], 1);
    g_pk[q] = make_float2(lt, rbits);
}

// ---- fma 4 halfs into fp32 accumulators ----
__device__ __forceinline__ void fma4(float* acc, uint2 p, float a) {
    __half2 h0 = *(__half2*)&p.x;
    __half2 h1 = *(__half2*)&p.y;
    float2 f0 = __half22float2(h0);
    float2 f1 = __half22float2(h1);
    acc[0] += a * f0.x; acc[1] += a * f0.y;
    acc[2] += a * f1.x; acc[3] += a * f1.y;
}

// ---- segment softmax + weighted msg accumulation (128-dim, fp16 rows) ----
__device__ __forceinline__ void seg_accum(int base, int deg, int lane, float* acc) {
    if (deg <= 0) return;
    if (deg <= 32) {
        float l = -CUDART_INF_F;
        int r = 0;
        if (lane < deg) {
            float2 pk = g_pk[base + lane];
            l = pk.x;
            r = __float_as_int(pk.y);
        }
        float m = l;
        #pragma unroll
        for (int o = 16; o; o >>= 1) m = fmaxf(m, __shfl_xor_sync(0xFFFFFFFFu, m, o));
        float z = (lane < deg) ? __expf(l - m) : 0.0f;
        float s = z;
        #pragma unroll
        for (int o = 16; o; o >>= 1) s += __shfl_xor_sync(0xFFFFFFFFu, s, o);
        float a_own = z / (s + 1e-16f);
        for (int j = 0; j < deg; j++) {
            float a = __shfl_sync(0xFFFFFFFFu, a_own, j);
            int rj  = __shfl_sync(0xFFFFFFFFu, r, j);
            uint2 p = ((const uint2*)(g_msg16 + (size_t)rj * HID))[lane];
            fma4(acc, p, a);
        }
    } else {
        float m = -CUDART_INF_F;
        for (int j = lane; j < deg; j += 32) m = fmaxf(m, g_pk[base + j].x);
        #pragma unroll
        for (int o = 16; o; o >>= 1) m = fmaxf(m, __shfl_xor_sync(0xFFFFFFFFu, m, o));
        float s = 0.0f;
        for (int j = lane; j < deg; j += 32) s += __expf(g_pk[base + j].x - m);
        #pragma unroll
        for (int o = 16; o; o >>= 1) s += __shfl_xor_sync(0xFFFFFFFFu, s, o);
        float inv = 1.0f / (s + 1e-16f);
        for (int c0 = 0; c0 < deg; c0 += 32) {
            int j = c0 + lane;
            float a_own = 0.0f;
            int r = 0;
            if (j < deg) {
                float2 pk = g_pk[base + j];
                a_own = __expf(pk.x - m) * inv;
                r = __float_as_int(pk.y);
            }
            int cnt = min(32, deg - c0);
            for (int jj = 0; jj < cnt; jj++) {
                float a = __shfl_sync(0xFFFFFFFFu, a_own, jj);
                int rj  = __shfl_sync(0xFFFFFFFFu, r, jj);
                uint2 p = ((const uint2*)(g_msg16 + (size_t)rj * HID))[lane];
                fma4(acc, p, a);
            }
        }
    }
}

// ---- gather: one warp per node, both directions -> fp16 agg row ----
__global__ void k_gather() {
    int n = (blockIdx.x * blockDim.x + threadIdx.x) >> 5;
    int lane = threadIdx.x & 31;
    if (n >= NE) return;

    float ah[4] = {0.f, 0.f, 0.f, 0.f};
    float at[4] = {0.f, 0.f, 0.f, 0.f};
    seg_accum(g_off[n],      g_hist[n],      lane, ah);
    seg_accum(g_off[NE + n], g_hist[NE + n], lane, at);

    __half2 h0 = __floats2half2_rn(ah[0], ah[1]);
    __half2 h1 = __floats2half2_rn(ah[2], ah[3]);
    __half2 t0 = __floats2half2_rn(at[0], at[1]);
    __half2 t1 = __floats2half2_rn(at[2], at[3]);
    __half* row = g_agg + (size_t)n * OUTD;
    *(uint2*)&row[lane * 4]       = make_uint2(*(unsigned*)&h0, *(unsigned*)&h1);
    *(uint2*)&row[HID + lane * 4] = make_uint2(*(unsigned*)&t0, *(unsigned*)&t1);
}

// ---- output GEMM: out = agg @ W_r + b_r via mma.sync m16n8k16 fp16 ----
// grid (196, 4); block 128 = 4 warps; each warp 8 strips of 16 rows; N=64/block.
__global__ __launch_bounds__(128) void k_gemm(const float* __restrict__ br,
                                              float* __restrict__ out) {
    __shared__ uint2 wf[16 * 8 * 32];   // 32 KB fragment buffer
    int tid = threadIdx.x, lane = tid & 31, wid = tid >> 5;
    int ns = blockIdx.y;                // n-split 0..3

    for (int i = tid; i < 16 * 8 * 32; i += 128) {
        int l = i & 31, nt = (i >> 5) & 7, kt = i >> 8;
        wf[i] = g_wf[(kt * 32 + ns * 8 + nt) * 32 + l];
    }
    __syncthreads();

    int kc = (lane & 3) * 2;
    int r  = lane >> 2;

    float2 bias[8];
    #pragma unroll
    for (int nt = 0; nt < 8; nt++)
        bias[nt] = *(const float2*)&br[ns * 64 + nt * 8 + kc];

    for (int s = 0; s < 8; s++) {
        int strip = blockIdx.x * 32 + s * 4 + wid;
        if (strip >= NSTRIP) break;
        size_t m0 = (size_t)strip * 16;
        const __half* A = g_agg + m0 * OUTD;

        float c[8][4];
        #pragma unroll
        for (int nt = 0; nt < 8; nt++)
            c[nt][0] = c[nt][1] = c[nt][2] = c[nt][3] = 0.f;

        #pragma unroll
        for (int kt = 0; kt < 16; kt++) {
            int k = kt * 16 + kc;
            unsigned a0 = *(const unsigned*)&A[(size_t)r * OUTD + k];
            unsigned a1 = *(const unsigned*)&A[(size_t)(r + 8) * OUTD + k];
            unsigned a2 = *(const unsigned*)&A[(size_t)r * OUTD + k + 8];
            unsigned a3 = *(const unsigned*)&A[(size_t)(r + 8) * OUTD + k + 8];
            #pragma unroll
            for (int nt = 0; nt < 8; nt++) {
                uint2 b = wf[(kt * 8 + nt) * 32 + lane];
                asm volatile(
                    "mma.sync.aligned.m16n8k16.row.col.f32.f16.f16.f32 "
                    "{%0,%1,%2,%3}, {%4,%5,%6,%7}, {%8,%9}, {%0,%1,%2,%3};"
                    : "+f"(c[nt][0]), "+f"(c[nt][1]), "+f"(c[nt][2]), "+f"(c[nt][3])
                    : "r"(a0), "r"(a1), "r"(a2), "r"(a3), "r"(b.x), "r"(b.y));
            }
        }

        #pragma unroll
        for (int nt = 0; nt < 8; nt++) {
            int n = ns * 64 + nt * 8 + kc;
            *(float2*)&out[(m0 + r) * 256 + n] =
                make_float2(c[nt][0] + bias[nt].x, c[nt][1] + bias[nt].y);
            *(float2*)&out[(m0 + r + 8) * 256 + n] =
                make_float2(c[nt][2] + bias[nt].x, c[nt][3] + bias[nt].y);
        }
    }
}

extern "C" void kernel_launch(void* const* d_in, const int* in_sizes, int n_in,
                              void* d_out, int out_size) {
    const float* x_e  = (const float*)d_in[0];
    const float* x_r  = (const float*)d_in[1];
    const int*   ei   = (const int*)d_in[2];
    const int*   rel  = (const int*)d_in[3];
    const float* w_ah = (const float*)d_in[5];
    const float* w_at = (const float*)d_in[6];
    const float* w_ar = (const float*)d_in[7];
    const float* W1   = (const float*)d_in[8];
    const float* b1   = (const float*)d_in[9];
    const float* W2   = (const float*)d_in[10];
    const float* b2   = (const float*)d_in[11];
    const float* Wr   = (const float*)d_in[12];
    const float* br   = (const float*)d_in[13];
    float* out = (float*)d_out;

    k_zero<<<(N2 + 1023) / 1024, 1024>>>();
    k_wf<<<32, 512>>>(Wr);
    k_front<<<FRONT_NB, 1024>>>(x_r, W1, b1, W2, b2, x_e, w_ah, w_at, w_ar, ei);
    k_scan1<<<SCAN_NB, SCAN_B>>>();
    k_scan2<<<1, 256>>>();
    k_scan3<<<(N2 + 255) / 256, 256>>>();
    k_fill<<<(EC + 255) / 256, 256>>>(ei, rel);
    k_gather<<<(NE + 7) / 8, 256>>>();
    k_gemm<<<dim3((NSTRIP + 31) / 32, 4), 128>>>(br, out);
}

// round 16
// speedup vs baseline: 1.5843x; 1.5843x over previous
#include <cuda_runtime.h>
#include <cuda_fp16.h>
#include <math_constants.h>

#define NE 100000
#define NR 1000
#define EC 1000000
#define HID 128
#define OUTD 256
#define N2 (2 * NE)
#define SCAN_B 1024
#define SCAN_NB ((N2 + SCAN_B - 1) / SCAN_B)   // 196
#define RT 8                                    // relations per MLP block

// block-range dispatch for the fused front kernel
#define MLP_NB 125
#define NS_NB  ((NE + 31) / 32)                // 3125  (warp per node, 32 warps/block)
#define RS_NB  ((NR + 31) / 32)                // 32
#define H_NB   ((EC + 1023) / 1024)            // 977   (histogram count blocks)
#define FRONT_NB (MLP_NB + NS_NB + RS_NB + H_NB)

// ---- scratch (device globals: allocation-free) ----
__device__ float  g_eh[NE];
__device__ float  g_et[NE];
__device__ float  g_er[NR];
__device__ __half g_tWh[NR * OUTD];
__device__ __half g_tWt[NR * OUTD];
__device__ int    g_hist[N2];
__device__ int    g_off[N2];
__device__ int    g_cur[N2];
__device__ float2 g_pk[2 * EC];        // per-slot packed (logit, rel-bits)
__device__ int    g_gtotal;            // global slot cursor for range allocation

// ---- zero histograms + global cursor (must precede front's hist blocks) ----
__global__ void k_zero() {
    int i = blockIdx.x * 1024 + threadIdx.x;
    if (i < N2) g_hist[i] = 0;
    if (i == 0) g_gtotal = 0;
}

// ---- fused front kernel: MLP + node_scores + rel_scores + hist count ----
__global__ __launch_bounds__(1024) void k_front(
        const float* __restrict__ xr,
        const float* __restrict__ W1, const float* __restrict__ b1,
        const float* __restrict__ W2, const float* __restrict__ b2,
        const float* __restrict__ Wr,
        const float* __restrict__ xe,
        const float* __restrict__ wah, const float* __restrict__ wat,
        const float* __restrict__ war,
        const int* __restrict__ ei) {
    __shared__ float xs[RT][HID];        // x_r rows; becomes msg after layer 2
    __shared__ float hs[RT][2 * HID];    // hidden layer
    __shared__ float red[8192];          // 32 KB reduction buffer
    int bid = blockIdx.x;
    int tid = threadIdx.x;               // 1024 threads

    if (bid < MLP_NB) {
        // ================= fused relation MLP + W_r fold =================
        int r0 = bid * RT;
        int rh = tid >> 8;               // relation subset: rels rh*2, rh*2+1

        for (int i = tid; i < RT * HID; i += 1024) {
            int rr = i >> 7, c = i & 127;
            xs[rr][c] = xr[(size_t)(r0 + rr) * HID + c];
        }
        __syncthreads();

        // layer 1: hs[i][c] = b1[c] + sum_k xs[i][k] * W1[k*256+c]
        {
            int kk = (tid >> 6) & 3;     // k-group 0..3
            int u  = tid & 63;           // cols 4u..4u+3
            float4 acc[2];
            #pragma unroll
            for (int i = 0; i < 2; i++) acc[i] = make_float4(0.f, 0.f, 0.f, 0.f);
            #pragma unroll 4
            for (int m = 0; m < 32; m++) {
                int k = kk + 4 * m;
                float4 w = *(const float4*)&W1[k * 256 + 4 * u];
                #pragma unroll
                for (int i = 0; i < 2; i++) {
                    float x = xs[rh * 2 + i][k];
                    acc[i].x += x * w.x; acc[i].y += x * w.y;
                    acc[i].z += x * w.z; acc[i].w += x * w.w;
                }
            }
            #pragma unroll
            for (int i = 0; i < 2; i++)
                *(float4*)&red[(kk * 8 + rh * 2 + i) * 256 + 4 * u] = acc[i];
            __syncthreads();
            #pragma unroll
            for (int p = 0; p < 2; p++) {
                int idx = p * 1024 + tid;      // 2048 outputs
                int i = idx >> 8, c = idx & 255;
                hs[i][c] = b1[c] + red[(0 + i) * 256 + c] + red[(8 + i) * 256 + c]
                         + red[(16 + i) * 256 + c] + red[(24 + i) * 256 + c];
            }
            __syncthreads();
        }

        // layer 2 + residual
        {
            int jj = (tid >> 5) & 7;     // j-group 0..7
            int u  = tid & 31;           // cols 4u..4u+3
            float4 acc[2];
            #pragma unroll
            for (int i = 0; i < 2; i++) acc[i] = make_float4(0.f, 0.f, 0.f, 0.f);
            #pragma unroll 4
            for (int m = 0; m < 32; m++) {
                int j = jj + 8 * m;
                float4 w = *(const float4*)&W2[j * 128 + 4 * u];
                #pragma unroll
                for (int i = 0; i < 2; i++) {
                    float x = hs[rh * 2 + i][j];
                    acc[i].x += x * w.x; acc[i].y += x * w.y;
                    acc[i].z += x * w.z; acc[i].w += x * w.w;
                }
            }
            #pragma unroll
            for (int i = 0; i < 2; i++)
                *(float4*)&red[(jj * 8 + rh * 2 + i) * 128 + 4 * u] = acc[i];
            __syncthreads();
            {
                int idx = tid;                 // 1024 outputs
                int i = idx >> 7, c = idx & 127;
                float v = b2[c];
                #pragma unroll
                for (int g = 0; g < 8; g++) v += red[(g * 8 + i) * 128 + c];
                xs[i][c] += v;                 // msg = x_r + mlp(x_r)
            }
            __syncthreads();
        }

        // layer 3: folded tables
        {
            int half = (tid >> 7) & 1;   // 0: h-table, 1: t-table
            int kk   = (tid >> 6) & 1;   // k-group 0,1
            int u    = tid & 63;         // cols 4u..4u+3
            float4 acc[2];
            #pragma unroll
            for (int i = 0; i < 2; i++) acc[i] = make_float4(0.f, 0.f, 0.f, 0.f);
            #pragma unroll 4
            for (int m = 0; m < 64; m++) {
                int k = kk + 2 * m;
                float4 w = *(const float4*)&Wr[(half * 128 + k) * 256 + 4 * u];
                #pragma unroll
                for (int i = 0; i < 2; i++) {
                    float x = xs[rh * 2 + i][k];
                    acc[i].x += x * w.x; acc[i].y += x * w.y;
                    acc[i].z += x * w.z; acc[i].w += x * w.w;
                }
            }
            #pragma unroll
            for (int i = 0; i < 2; i++)
                *(float4*)&red[((kk * 2 + half) * 8 + rh * 2 + i) * 256 + 4 * u] = acc[i];
            __syncthreads();
            #pragma unroll
            for (int p = 0; p < 4; p++) {
                int idx = p * 1024 + tid;      // 4096 outputs
                int c = idx & 255;
                int q = idx >> 8;              // 0..15
                int i = q & 7, hf = q >> 3;
                float v = red[((0 + hf) * 8 + i) * 256 + c]
                        + red[((2 + hf) * 8 + i) * 256 + c];
                if (hf == 0) g_tWh[(size_t)(r0 + i) * OUTD + c] = __float2half(v);
                else         g_tWt[(size_t)(r0 + i) * OUTD + c] = __float2half(v);
            }
        }
    } else if (bid < MLP_NB + NS_NB) {
        // ================= per-entity attention scores (warp per node) =====
        int warp = (bid - MLP_NB) * 32 + (tid >> 5);
        int lane = tid & 31;
        if (warp < NE) {
            const float4* row = (const float4*)(xe + (size_t)warp * HID);
            float4 v = row[lane];
            float4 a = ((const float4*)wah)[lane];
            float4 b = ((const float4*)wat)[lane];
            float sh = v.x * a.x + v.y * a.y + v.z * a.z + v.w * a.w;
            float st = v.x * b.x + v.y * b.y + v.z * b.z + v.w * b.w;
            #pragma unroll
            for (int o = 16; o; o >>= 1) {
                sh += __shfl_xor_sync(0xFFFFFFFFu, sh, o);
                st += __shfl_xor_sync(0xFFFFFFFFu, st, o);
            }
            if (lane == 0) { g_eh[warp] = sh; g_et[warp] = st; }
        }
    } else if (bid < MLP_NB + NS_NB + RS_NB) {
        // ================= per-relation attention scores (warp per rel) ====
        int warp = (bid - MLP_NB - NS_NB) * 32 + (tid >> 5);
        int lane = tid & 31;
        if (warp < NR) {
            const float4* row = (const float4*)(xr + (size_t)warp * HID);
            float4 v = row[lane];
            float4 a = ((const float4*)war)[lane];
            float s = v.x * a.x + v.y * a.y + v.z * a.z + v.w * a.w;
            #pragma unroll
            for (int o = 16; o; o >>= 1) s += __shfl_xor_sync(0xFFFFFFFFu, s, o);
            if (lane == 0) g_er[warp] = s;
        }
    } else {
        // ================= degree histogram (needs only ei) ================
        int e = (bid - MLP_NB - NS_NB - RS_NB) * 1024 + tid;
        if (e < EC) {
            atomicAdd(&g_hist[ei[e]], 1);
            atomicAdd(&g_hist[NE + ei[EC + e]], 1);
        }
    }
}

// ---- single-kernel scan: block-local exclusive scan + atomic range base ----
// CSR bases need only be DISJOINT, not ordered; gather consumes (off, deg)
// pairs independently, so block ranges are allocated via one atomicAdd each.
__global__ void k_scan() {
    __shared__ int sh[SCAN_B];
    __shared__ int sbase;
    int t = threadIdx.x;
    int i = blockIdx.x * SCAN_B + t;
    int v = (i < N2) ? g_hist[i] : 0;
    sh[t] = v;
    __syncthreads();
    #pragma unroll
    for (int d = 1; d < SCAN_B; d <<= 1) {
        int x = (t >= d) ? sh[t - d] : 0;
        __syncthreads();
        sh[t] += x;
        __syncthreads();
    }
    if (t == SCAN_B - 1) sbase = atomicAdd(&g_gtotal, sh[t]);
    __syncthreads();
    if (i < N2) {
        int o = sbase + sh[t] - v;     // exclusive within block + block base
        g_off[i] = o;
        g_cur[i] = o;
    }
}

// ---- fused CSR fill + logits: writes packed (logit, rel) per slot ----
__global__ void k_fill(const int* __restrict__ ei, const int* __restrict__ rel) {
    int e = blockIdx.x * blockDim.x + threadIdx.x;
    if (e >= EC) return;
    int h = ei[e], t = ei[EC + e], r = rel[e];
    float er = g_er[r];
    float rbits = __int_as_float(r);
    float lh = g_eh[h] + er;
    lh = lh > 0.0f ? lh : 0.01f * lh;
    float lt = g_et[t] + er;
    lt = lt > 0.0f ? lt : 0.01f * lt;
    int p = atomicAdd(&g_cur[h], 1);
    g_pk[p] = make_float2(lh, rbits);
    int q = atomicAdd(&g_cur[NE + t], 1);
    g_pk[q] = make_float2(lt, rbits);
}

// ---- fma 8 halfs into fp32 accumulators ----
__device__ __forceinline__ void fma8(float* acc, uint4 p, float a) {
    __half2* h = reinterpret_cast<__half2*>(&p);
    #pragma unroll
    for (int q = 0; q < 4; q++) {
        float2 f = __half22float2(h[q]);
        acc[2 * q]     += a * f.x;
        acc[2 * q + 1] += a * f.y;
    }
}

// ---- segment softmax + weighted half-table accumulation (packed slots) ----
__device__ __forceinline__ void seg_accum(int base, int deg, int lane,
                                          const __half* __restrict__ table,
                                          float* acc) {
    if (deg <= 0) return;
    if (deg <= 32) {
        float l = -CUDART_INF_F;
        int r = 0;
        if (lane < deg) {
            float2 pk = g_pk[base + lane];     // one coalesced 8B load
            l = pk.x;
            r = __float_as_int(pk.y);
        }
        float m = l;
        #pragma unroll
        for (int o = 16; o; o >>= 1) m = fmaxf(m, __shfl_xor_sync(0xFFFFFFFFu, m, o));
        float z = (lane < deg) ? __expf(l - m) : 0.0f;
        float s = z;
        #pragma unroll
        for (int o = 16; o; o >>= 1) s += __shfl_xor_sync(0xFFFFFFFFu, s, o);
        float a_own = z / (s + 1e-16f);
        for (int j = 0; j < deg; j++) {
            float a = __shfl_sync(0xFFFFFFFFu, a_own, j);
            int rj  = __shfl_sync(0xFFFFFFFFu, r, j);
            uint4 p = ((const uint4*)(table + (size_t)rj * OUTD))[lane];
            fma8(acc, p, a);
        }
    } else {
        float m = -CUDART_INF_F;
        for (int j = lane; j < deg; j += 32) m = fmaxf(m, g_pk[base + j].x);
        #pragma unroll
        for (int o = 16; o; o >>= 1) m = fmaxf(m, __shfl_xor_sync(0xFFFFFFFFu, m, o));
        float s = 0.0f;
        for (int j = lane; j < deg; j += 32) s += __expf(g_pk[base + j].x - m);
        #pragma unroll
        for (int o = 16; o; o >>= 1) s += __shfl_xor_sync(0xFFFFFFFFu, s, o);
        float inv = 1.0f / (s + 1e-16f);
        for (int c0 = 0; c0 < deg; c0 += 32) {
            int j = c0 + lane;
            float a_own = 0.0f;
            int r = 0;
            if (j < deg) {
                float2 pk = g_pk[base + j];
                a_own = __expf(pk.x - m) * inv;
                r = __float_as_int(pk.y);
            }
            int cnt = min(32, deg - c0);
            for (int jj = 0; jj < cnt; jj++) {
                float a = __shfl_sync(0xFFFFFFFFu, a_own, jj);
                int rj  = __shfl_sync(0xFFFFFFFFu, r, jj);
                uint4 p = ((const uint4*)(table + (size_t)rj * OUTD))[lane];
                fma8(acc, p, a);
            }
        }
    }
}

// ---- gather: one warp per node, both directions, single row store ----
__global__ void k_gather(const float* __restrict__ br, float* __restrict__ out) {
    int n = (blockIdx.x * blockDim.x + threadIdx.x) >> 5;
    int lane = threadIdx.x & 31;
    if (n >= NE) return;

    float acc[8];
    #pragma unroll
    for (int q = 0; q < 8; q++) acc[q] = 0.0f;

    seg_accum(g_off[n],      g_hist[n],      lane, g_tWh, acc);
    seg_accum(g_off[NE + n], g_hist[NE + n], lane, g_tWt, acc);

    float4 b0 = ((const float4*)(br + lane * 8))[0];
    float4 b1 = ((const float4*)(br + lane * 8))[1];
    float4* o = (float4*)(out + (size_t)n * OUTD + lane * 8);
    o[0] = make_float4(acc[0] + b0.x, acc[1] + b0.y, acc[2] + b0.z, acc[3] + b0.w);
    o[1] = make_float4(acc[4] + b1.x, acc[5] + b1.y, acc[6] + b1.z, acc[7] + b1.w);
}

extern "C" void kernel_launch(void* const* d_in, const int* in_sizes, int n_in,
                              void* d_out, int out_size) {
    const float* x_e  = (const float*)d_in[0];
    const float* x_r  = (const float*)d_in[1];
    const int*   ei   = (const int*)d_in[2];
    const int*   rel  = (const int*)d_in[3];
    const float* w_ah = (const float*)d_in[5];
    const float* w_at = (const float*)d_in[6];
    const float* w_ar = (const float*)d_in[7];
    const float* W1   = (const float*)d_in[8];
    const float* b1   = (const float*)d_in[9];
    const float* W2   = (const float*)d_in[10];
    const float* b2   = (const float*)d_in[11];
    const float* Wr   = (const float*)d_in[12];
    const float* br   = (const float*)d_in[13];
    float* out = (float*)d_out;

    k_zero<<<(N2 + 1023) / 1024, 1024>>>();
    k_front<<<FRONT_NB, 1024>>>(x_r, W1, b1, W2, b2, Wr, x_e, w_ah, w_at, w_ar, ei);
    k_scan<<<SCAN_NB, SCAN_B>>>();
    k_fill<<<(EC + 255) / 256, 256>>>(ei, rel);
    k_gather<<<(NE + 7) / 8, 256>>>(br, out);
}